// round 1
// baseline (speedup 1.0000x reference)
#include <cuda_runtime.h>

#define BIN      1025
#define NFFT     2048
#define THREADS  256
#define DPI      3.14159265358979323846

// ---------------- precomputed tables (filled by init kernel each launch) ----
__device__ float g_twr[1023];   // staged twiddles: stage h at [h-1, 2h-1), exp(-i*pi*t/h)
__device__ float g_twi[1023];
__device__ float g_hc[1025];    // cos(pi*k/1024)
__device__ float g_hs[1025];    // sin(pi*k/1024)

__global__ void init_tables() {
    int tid = blockIdx.x * blockDim.x + threadIdx.x;
    int nt  = gridDim.x * blockDim.x;
    for (int idx = tid; idx < 1023; idx += nt) {
        // h = pow2 with idx in [h-1, 2h-1)
        int h = 1;
        while ((2 * h - 1) <= idx) h <<= 1;
        int t = idx - (h - 1);
        double ang = -DPI * (double)t / (double)h;   // -2*pi*t/(2h)
        g_twr[idx] = (float)cos(ang);
        g_twi[idx] = (float)sin(ang);
    }
    for (int k = tid; k < 1025; k += nt) {
        double th = DPI * (double)k / 1024.0;
        g_hc[k] = (float)cos(th);
        g_hs[k] = (float)sin(th);
    }
}

// ---------------- main kernel: one row at a time per CTA (persistent) -------
// Per row:
//   u = log(x)                               (1025)
//   U = DCT1_2048(u)  == rfft(sym_ext(u)).real, via complex-1024 packing
//   L = U * sm[f0] * cp[f0]
//   out = DCT1_2048(L) / 2048
__global__ void __launch_bounds__(THREADS)
cheaptrick_kernel(const float* __restrict__ x,
                  const int*   __restrict__ f0,
                  const float* __restrict__ sm,
                  const float* __restrict__ cp,
                  float*       __restrict__ out,
                  int n_rows)
{
    __shared__ float s_twr[1023], s_twi[1023];
    __shared__ float s_hc[1025],  s_hs[1025];
    __shared__ float s_vr[1024],  s_vi[1024];
    __shared__ float s_u[1025];

    const int tid  = threadIdx.x;
    const int lane = tid & 31;
    const int warp = tid >> 5;

    // load tables once per CTA
    for (int i = tid; i < 1023; i += THREADS) { s_twr[i] = g_twr[i]; s_twi[i] = g_twi[i]; }
    for (int i = tid; i < 1025; i += THREADS) { s_hc[i]  = g_hc[i];  s_hs[i]  = g_hs[i];  }
    __syncthreads();

    for (int r = blockIdx.x; r < n_rows; r += gridDim.x) {
        const float* xr   = x  + (size_t)r * BIN;
        const int    f    = f0[r];
        const float* smr  = sm + (size_t)f * BIN;
        const float* cpr  = cp + (size_t)f * BIN;
        float*       outr = out + (size_t)r * BIN;

        // ---- log(x) into s_u ----
        for (int i = tid; i < BIN; i += THREADS) s_u[i] = __logf(xr[i]);
        __syncthreads();

        #pragma unroll
        for (int pass = 0; pass < 2; pass++) {
            // ---- pack: z[j] = s[2j] + i*s[2j+1] of symmetric extension,
            //      written to bit-reversed position (DIT input).
            //      j = 32*lane + ((lane + c) & 31): low 5 bits AND high 5 bits
            //      distinct within a warp -> conflict-free read & bitrev write.
            #pragma unroll
            for (int cc = 0; cc < 4; cc++) {
                int c  = warp + cc * 8;
                int j  = (lane << 5) | ((lane + c) & 31);
                int rj = __brev((unsigned)j) >> 22;
                int i0 = 2 * j, i1 = 2 * j + 1;
                float a = s_u[(i0 <= 1024) ? i0 : (NFFT - i0)];
                float b = s_u[(i1 <= 1024) ? i1 : (NFFT - i1)];
                s_vr[rj] = a;
                s_vi[rj] = b;
            }

            // ---- 1024-pt complex FFT, radix-2 DIT (bit-reversed in, natural out)
            #pragma unroll
            for (int s = 0; s < 10; s++) {
                const int h = 1 << s;
                __syncthreads();
                #pragma unroll
                for (int q = 0; q < 2; q++) {
                    int p  = tid + q * THREADS;       // butterfly id 0..511
                    int t  = p & (h - 1);
                    int i0 = ((p - t) << 1) + t;
                    int i1 = i0 + h;
                    float wr = s_twr[h - 1 + t];
                    float wi = s_twi[h - 1 + t];
                    float br = s_vr[i1], bi = s_vi[i1];
                    float tr = br * wr - bi * wi;
                    float ti = br * wi + bi * wr;
                    float ar = s_vr[i0], ai = s_vi[i0];
                    s_vr[i0] = ar + tr;  s_vi[i0] = ai + ti;
                    s_vr[i1] = ar - tr;  s_vi[i1] = ai - ti;
                }
            }
            __syncthreads();

            // ---- untangle: U[k] = Re( E[k] + e^{-i*pi*k/1024} O[k] )
            //   E = (Z[k] + conj(Z[1024-k]))/2,  O = (Z[k] - conj(Z[1024-k]))/(2i)
            //   => U = Er + cos*Or + sin*Oi  with
            //      Er=(Zr+Z2r)/2, Or=(Zi+Z2i)/2, Oi=(Z2r-Zr)/2
            if (pass == 0) {
                for (int k = tid; k <= 1024; k += THREADS) {
                    int kk = k & 1023, k2 = (1024 - k) & 1023;
                    float Zr  = s_vr[kk], Zi  = s_vi[kk];
                    float Z2r = s_vr[k2], Z2i = s_vi[k2];
                    float Er = 0.5f * (Zr + Z2r);
                    float Or = 0.5f * (Zi + Z2i);
                    float Oi = 0.5f * (Z2r - Zr);
                    float U  = Er + s_hc[k] * Or + s_hs[k] * Oi;
                    s_u[k] = U * smr[k] * cpr[k];     // liftered cepstrum
                }
                __syncthreads();
            } else {
                for (int k = tid; k <= 1024; k += THREADS) {
                    int kk = k & 1023, k2 = (1024 - k) & 1023;
                    float Zr  = s_vr[kk], Zi  = s_vi[kk];
                    float Z2r = s_vr[k2], Z2i = s_vi[k2];
                    float Er = 0.5f * (Zr + Z2r);
                    float Or = 0.5f * (Zi + Z2i);
                    float Oi = 0.5f * (Z2r - Zr);
                    float U  = Er + s_hc[k] * Or + s_hs[k] * Oi;
                    outr[k] = U * (1.0f / (float)NFFT);
                }
                __syncthreads();
            }
        }
    }
}

extern "C" void kernel_launch(void* const* d_in, const int* in_sizes, int n_in,
                              void* d_out, int out_size) {
    const float* x  = (const float*)d_in[0];
    const int*   f0 = (const int*)  d_in[1];
    const float* sm = (const float*)d_in[2];
    const float* cp = (const float*)d_in[3];
    float* out = (float*)d_out;
    const int n_rows = in_sizes[1];          // B*T (f0 element count)

    init_tables<<<4, 256>>>();
    cheaptrick_kernel<<<592, THREADS>>>(x, f0, sm, cp, out, n_rows);
}

// round 2
// speedup vs baseline: 2.3790x; 2.3790x over previous
#include <cuda_runtime.h>

#define BIN      1025
#define WARPS    4
#define THREADS  128
#define DPI      3.14159265358979323846

// ---------------- precomputed tables (filled by init kernel each launch) ----
__device__ float2 g_tw1024[1024];   // [k2*32+n1] = exp(-2*pi*i*n1*k2/1024)
__device__ float2 g_hb32[32];       // (cos(pi*j/32), sin(pi*j/32))

__global__ void init_tables() {
    int t = blockIdx.x * blockDim.x + threadIdx.x;
    if (t < 1024) {
        int k2 = t >> 5, n1 = t & 31;
        double ang = -2.0 * DPI * (double)(n1 * k2) / 1024.0;
        g_tw1024[t] = make_float2((float)cos(ang), (float)sin(ang));
    }
    if (t < 32) {
        double b = DPI * (double)t / 32.0;
        g_hb32[t] = make_float2((float)cos(b), (float)sin(b));
    }
}

// W32[m] = exp(-2*pi*i*m/32); compile-time twiddles for the register FFT
__device__ constexpr float W32R[16] = {
    1.0f,                   0.980785280403230449f,  0.923879532511286756f,  0.831469612302545237f,
    0.707106781186547524f,  0.555570233019602225f,  0.382683432365089772f,  0.195090322016128268f,
    0.0f,                  -0.195090322016128268f, -0.382683432365089772f, -0.555570233019602225f,
   -0.707106781186547524f, -0.831469612302545237f, -0.923879532511286756f, -0.980785280403230449f };
__device__ constexpr float W32I[16] = {
   -0.0f,                  -0.195090322016128268f, -0.382683432365089772f, -0.555570233019602225f,
   -0.707106781186547524f, -0.831469612302545237f, -0.923879532511286756f, -0.980785280403230449f,
   -1.0f,                  -0.980785280403230449f, -0.923879532511286756f, -0.831469612302545237f,
   -0.707106781186547524f, -0.555570233019602225f, -0.382683432365089772f, -0.195090322016128268f };

__device__ __host__ constexpr int brev5(int n) {
    return ((n & 1) << 4) | ((n & 2) << 2) | (n & 4) | ((n >> 2) & 2) | ((n >> 4) & 1);
}

// 32-pt complex FFT in registers, radix-2 DIT.
// Input must be loaded in bit-reversed register order; output natural order.
__device__ __forceinline__ void fft32(float re[32], float im[32]) {
    #pragma unroll
    for (int s = 0; s < 5; s++) {
        const int h = 1 << s;
        #pragma unroll
        for (int p = 0; p < 16; p++) {
            const int t  = p & (h - 1);
            const int i0 = ((p - t) << 1) + t;
            const int i1 = i0 + h;
            const int m  = t << (4 - s);
            const float wr = W32R[m], wi = W32I[m];
            float br = re[i1], bi = im[i1];
            float tr = br * wr - bi * wi;
            float ti = br * wi + bi * wr;
            float ar = re[i0], ai = im[i0];
            re[i0] = ar + tr;  im[i0] = ai + ti;
            re[i1] = ar - tr;  im[i1] = ai - ti;
        }
    }
}

// ---------------- main kernel: one WARP per row (warp-autonomous) ----------
// Per row:  u = log x;  U = DCT1_2048(u) via complex-1024 packing with the
// 32x32 Cooley-Tukey split (two register FFTs + 1 smem transpose);
// L = U*sm[f0]*cp[f0];  out = DCT1_2048(L)/2048.
__global__ void __launch_bounds__(THREADS)
cheaptrick_kernel(const float* __restrict__ x,
                  const int*   __restrict__ f0,
                  const float* __restrict__ sm,
                  const float* __restrict__ cp,
                  float*       __restrict__ out,
                  int n_rows)
{
    __shared__ float2 s_tw[1024];            // 8 KB, CTA-shared
    __shared__ float2 s_hb[32];
    __shared__ float  s_tr[WARPS * 2112];    // per warp: re[1056] + im[1056] (32x33 padded)

    const int tid  = threadIdx.x;
    const int lane = tid & 31;
    const int warp = tid >> 5;

    for (int i = tid; i < 1024; i += THREADS) s_tw[i] = g_tw1024[i];
    if (tid < 32) s_hb[tid] = g_hb32[tid];
    __syncthreads();

    float* trR = s_tr + warp * 2112;
    float* trI = trR + 1056;
    float* sL  = trR;                        // reuse re-buffer as the 1025-pt L buffer

    float ca, sa;                            // cos/sin(pi*lane/1024)
    __sincosf((float)(DPI / 1024.0) * (float)lane, &sa, &ca);

    const int nwarps = gridDim.x * WARPS;
    const int gw     = blockIdx.x * WARPS + warp;

    for (int r = gw; r < n_rows; r += nwarps) {
        const float* xr  = x  + (size_t)r * BIN;
        const int    f   = f0[r];
        const float* smr = sm + (size_t)f * BIN;
        const float* cpr = cp + (size_t)f * BIN;
        float*       outr = out + (size_t)r * BIN;

        float re[32], im[32];

        #pragma unroll 2
        for (int pass = 0; pass < 2; pass++) {
            // ---- pack z[j]=s[2j]+i*s[2j+1] of the even-symmetric extension;
            //      j = lane + 32*n2, stored bit-reversed in registers (DIT input)
            #pragma unroll
            for (int n2 = 0; n2 < 32; n2++) {
                int i0 = 2 * lane + 64 * n2;
                int i1 = i0 + 1;
                if (i0 > 1024) i0 = 2048 - i0;
                if (i1 > 1024) i1 = 2048 - i1;
                if (pass == 0) {
                    re[brev5(n2)] = __logf(__ldg(xr + i0));
                    im[brev5(n2)] = __logf(__ldg(xr + i1));
                } else {
                    re[brev5(n2)] = sL[i0];
                    im[brev5(n2)] = sL[i1];
                }
            }
            __syncwarp();

            // ---- inner 32-pt FFT over n2 (lane = n1) ----
            fft32(re, im);

            // ---- 1024-pt twiddle + transpose (32x33 padded, conflict-free) ----
            #pragma unroll
            for (int k2 = 0; k2 < 32; k2++) {
                float2 w  = s_tw[k2 * 32 + lane];
                float  yr = re[k2] * w.x - im[k2] * w.y;
                float  yi = re[k2] * w.y + im[k2] * w.x;
                trR[lane * 33 + k2] = yr;
                trI[lane * 33 + k2] = yi;
            }
            __syncwarp();
            #pragma unroll
            for (int n1 = 0; n1 < 32; n1++) {
                re[brev5(n1)] = trR[n1 * 33 + lane];
                im[brev5(n1)] = trI[n1 * 33 + lane];
            }
            __syncwarp();

            // ---- outer 32-pt FFT over n1 (lane = k2, reg = k1 natural) ----
            fft32(re, im);
            // Z[k2 + 32*k1] now at lane k2, register k1.

            // ---- untangle to U[k] = Re(E + e^{-i*pi*k/1024} O), k = lane + 32*j
            //      partner Z[(1024-k) mod 1024] = (lane (32-l)&31, reg 31-j); lane 0 local
            const int src = (32 - lane) & 31;
            #pragma unroll
            for (int j = 0; j < 32; j++) {
                float z2r = __shfl_sync(0xFFFFFFFFu, re[31 - j], src);
                float z2i = __shfl_sync(0xFFFFFFFFu, im[31 - j], src);
                if (lane == 0) { z2r = re[(32 - j) & 31]; z2i = im[(32 - j) & 31]; }
                float Er = 0.5f * (re[j] + z2r);
                float Or = 0.5f * (im[j] + z2i);
                float Oi = 0.5f * (z2r - re[j]);
                float2 hb = s_hb[j];                 // cos/sin(pi*j/32), broadcast
                float hc = ca * hb.x - sa * hb.y;    // cos(pi*k/1024)
                float hs = sa * hb.x + ca * hb.y;    // sin(pi*k/1024)
                float U  = Er + hc * Or + hs * Oi;
                int   k  = lane + 32 * j;
                if (pass == 0) {
                    sL[k] = U * __ldg(smr + k) * __ldg(cpr + k);
                } else {
                    outr[k] = U * (1.0f / 2048.0f);
                }
            }
            // k = 1024: U = Zr[0] - Zi[0] (lane 0 holds Z[0] in reg 0)
            float U1024 = re[0] - im[0];
            if (lane == 0) {
                if (pass == 0) sL[1024] = U1024 * __ldg(smr + 1024) * __ldg(cpr + 1024);
                else           outr[1024] = U1024 * (1.0f / 2048.0f);
            }
            __syncwarp();
        }
    }
}

extern "C" void kernel_launch(void* const* d_in, const int* in_sizes, int n_in,
                              void* d_out, int out_size) {
    const float* x  = (const float*)d_in[0];
    const int*   f0 = (const int*)  d_in[1];
    const float* sm = (const float*)d_in[2];
    const float* cp = (const float*)d_in[3];
    float* out = (float*)d_out;
    const int n_rows = in_sizes[1];          // B*T

    init_tables<<<4, 256>>>();
    cheaptrick_kernel<<<592, THREADS>>>(x, f0, sm, cp, out, n_rows);
}

// round 3
// speedup vs baseline: 3.1715x; 1.3331x over previous
#include <cuda_runtime.h>

#define BIN      1025
#define WARPS    4
#define THREADS  128
#define DPI      3.14159265358979323846

// ---------------- precomputed tables (filled by init kernel each launch) ----
__device__ float2 g_tw1024[1024];   // [k2*32+n1] = exp(-2*pi*i*n1*k2/1024)
__device__ float2 g_hb32[32];       // (cos(pi*j/32), sin(pi*j/32))

__global__ void init_tables() {
    int t = blockIdx.x * blockDim.x + threadIdx.x;
    if (t < 1024) {
        int k2 = t >> 5, n1 = t & 31;
        double ang = -2.0 * DPI * (double)(n1 * k2) / 1024.0;
        g_tw1024[t] = make_float2((float)cos(ang), (float)sin(ang));
    }
    if (t < 32) {
        double b = DPI * (double)t / 32.0;
        g_hb32[t] = make_float2((float)cos(b), (float)sin(b));
    }
}

// W32[m] = exp(-2*pi*i*m/32)
__device__ constexpr float W32R[16] = {
    1.0f,                   0.980785280403230449f,  0.923879532511286756f,  0.831469612302545237f,
    0.707106781186547524f,  0.555570233019602225f,  0.382683432365089772f,  0.195090322016128268f,
    0.0f,                  -0.195090322016128268f, -0.382683432365089772f, -0.555570233019602225f,
   -0.707106781186547524f, -0.831469612302545237f, -0.923879532511286756f, -0.980785280403230449f };
__device__ constexpr float W32I[16] = {
   -0.0f,                  -0.195090322016128268f, -0.382683432365089772f, -0.555570233019602225f,
   -0.707106781186547524f, -0.831469612302545237f, -0.923879532511286756f, -0.980785280403230449f,
   -1.0f,                  -0.980785280403230449f, -0.923879532511286756f, -0.831469612302545237f,
   -0.707106781186547524f, -0.555570233019602225f, -0.382683432365089772f, -0.195090322016128268f };

__device__ __host__ constexpr int brev5(int n) {
    return ((n & 1) << 4) | ((n & 2) << 2) | (n & 4) | ((n >> 2) & 2) | ((n >> 4) & 1);
}

// One radix-2 butterfly with twiddle W32^m; m is a compile-time constant after
// unrolling, so the trivial cases (m==0 -> w=1, m==8 -> w=-i) become pure
// add/sub with no FMAs.
__device__ __forceinline__ void bfly(float& ar, float& ai, float& br, float& bi, const int m) {
    float tr, ti;
    if (m == 0)      { tr = br;  ti = bi;  }
    else if (m == 8) { tr = bi;  ti = -br; }          // * -i
    else             { tr = br * W32R[m] - bi * W32I[m];
                       ti = br * W32I[m] + bi * W32R[m]; }
    float xr = ar, xi = ai;
    ar = xr + tr;  ai = xi + ti;
    br = xr - tr;  bi = xi - ti;
}

// 32-pt complex FFT in registers, radix-2 DIT (bit-reversed in, natural out).
__device__ __forceinline__ void fft32(float re[32], float im[32]) {
    #pragma unroll
    for (int s = 0; s < 5; s++) {
        const int h = 1 << s;
        #pragma unroll
        for (int p = 0; p < 16; p++) {
            const int t  = p & (h - 1);
            const int i0 = ((p - t) << 1) + t;
            const int i1 = i0 + h;
            const int m  = t << (4 - s);
            bfly(re[i0], im[i0], re[i1], im[i1], m);
        }
    }
}

// ---------------- main kernel: one WARP per row (warp-autonomous) ----------
__global__ void __launch_bounds__(THREADS, 4)
cheaptrick_kernel(const float* __restrict__ x,
                  const int*   __restrict__ f0,
                  const float* __restrict__ sm,
                  const float* __restrict__ cp,
                  float*       __restrict__ out,
                  int n_rows)
{
    __shared__ float2 s_tw[1024];            // 8 KB, CTA-shared
    __shared__ float2 s_hb[32];
    __shared__ float  s_buf[WARPS * 2112];   // per warp: transpose re[1056]+im[1056];
                                             // aliased: e[513] (buf[0..]), o[512] (buf[513..])

    const int tid  = threadIdx.x;
    const int lane = tid & 31;
    const int warp = tid >> 5;

    for (int i = tid; i < 1024; i += THREADS) s_tw[i] = g_tw1024[i];
    if (tid < 32) s_hb[tid] = g_hb32[tid];
    __syncthreads();

    float* buf = s_buf + warp * 2112;
    float* trR = buf;                        // [0 .. 1055]
    float* trI = buf + 1056;                 // [1056 .. 2111]
    float* sE  = buf;                        // e[m] = u[2m],   m in [0,512]
    float* sO  = buf + 513;                  // o[m] = u[2m+1], m in [0,511]
    // Lifetimes: within each pass, all e/o reads complete (into regs) before
    // the transpose writes; the untangle writes e/o only after the transpose
    // reads are consumed. __syncwarp() separates the phases (1 warp per row).

    float ca, sa;                            // cos/sin(pi*lane/1024)
    __sincosf((float)(DPI / 1024.0) * (float)lane, &sa, &ca);

    const int nwarps = gridDim.x * WARPS;
    const int gw     = blockIdx.x * WARPS + warp;

    for (int r = gw; r < n_rows; r += nwarps) {
        const float* xr  = x  + (size_t)r * BIN;
        const int    f   = f0[r];
        const float* smr = sm + (size_t)f * BIN;
        const float* cpr = cp + (size_t)f * BIN;
        float*       outr = out + (size_t)r * BIN;

        // ---- log once per unique bin into even/odd-split smem ----
        #pragma unroll
        for (int i = lane; i < BIN; i += 32) {
            float v = __logf(__ldg(xr + i));
            if (i & 1) sO[i >> 1] = v;
            else       sE[i >> 1] = v;
        }
        __syncwarp();

        float re[32], im[32];

        #pragma unroll 2
        for (int pass = 0; pass < 2; pass++) {
            // ---- pack z[j] = u[2j] + i*u[2j+1] (even-symmetric extension),
            //      j = lane + 32*n2, bit-reversed into registers.
            //      u[2j] = e[j<=512 ? j : 1024-j]; u[2j+1] = o[j<=511 ? j : 1023-j]
            #pragma unroll
            for (int n2 = 0; n2 < 32; n2++) {
                int j  = lane + 32 * n2;
                int ei = (j <= 512) ? j : (1024 - j);
                int oi = (j <= 511) ? j : (1023 - j);
                re[brev5(n2)] = sE[ei];
                im[brev5(n2)] = sO[oi];
            }
            __syncwarp();

            // ---- inner 32-pt FFT over n2 (lane = n1) ----
            fft32(re, im);

            // ---- 1024-pt twiddle + transpose (32x33 padded, conflict-free) ----
            #pragma unroll
            for (int k2 = 0; k2 < 32; k2++) {
                float2 w  = s_tw[k2 * 32 + lane];
                float  yr = re[k2] * w.x - im[k2] * w.y;
                float  yi = re[k2] * w.y + im[k2] * w.x;
                trR[lane * 33 + k2] = yr;
                trI[lane * 33 + k2] = yi;
            }
            __syncwarp();
            #pragma unroll
            for (int n1 = 0; n1 < 32; n1++) {
                re[brev5(n1)] = trR[n1 * 33 + lane];
                im[brev5(n1)] = trI[n1 * 33 + lane];
            }
            __syncwarp();

            // ---- outer 32-pt FFT over n1 (lane = k2, reg = k1) ----
            fft32(re, im);
            // Z[k2 + 32*k1] at lane k2, register k1.

            // ---- untangle: U[k] = Re(E + e^{-i*pi*k/1024} O), k = lane + 32*j
            const int src = (32 - lane) & 31;
            #pragma unroll
            for (int j = 0; j < 32; j++) {
                float z2r = __shfl_sync(0xFFFFFFFFu, re[31 - j], src);
                float z2i = __shfl_sync(0xFFFFFFFFu, im[31 - j], src);
                if (lane == 0) { z2r = re[(32 - j) & 31]; z2i = im[(32 - j) & 31]; }
                float Er = 0.5f * (re[j] + z2r);
                float Or = 0.5f * (im[j] + z2i);
                float Oi = 0.5f * (z2r - re[j]);
                float2 hb = s_hb[j];                 // broadcast
                float hc = ca * hb.x - sa * hb.y;    // cos(pi*k/1024)
                float hs = sa * hb.x + ca * hb.y;    // sin(pi*k/1024)
                float U  = Er + hc * Or + hs * Oi;
                int   k  = lane + 32 * j;
                if (pass == 0) {
                    float L = U * __ldg(smr + k) * __ldg(cpr + k);
                    if (k & 1) sO[k >> 1] = L;
                    else       sE[k >> 1] = L;
                } else {
                    outr[k] = U * (1.0f / 2048.0f);
                }
            }
            // k = 1024 (even): U = Zr[0] - Zi[0], held by lane 0 reg 0
            float U1024 = re[0] - im[0];
            if (lane == 0) {
                if (pass == 0) sE[512] = U1024 * __ldg(smr + 1024) * __ldg(cpr + 1024);
                else           outr[1024] = U1024 * (1.0f / 2048.0f);
            }
            __syncwarp();
        }
    }
}

extern "C" void kernel_launch(void* const* d_in, const int* in_sizes, int n_in,
                              void* d_out, int out_size) {
    const float* x  = (const float*)d_in[0];
    const int*   f0 = (const int*)  d_in[1];
    const float* sm = (const float*)d_in[2];
    const float* cp = (const float*)d_in[3];
    float* out = (float*)d_out;
    const int n_rows = in_sizes[1];          // B*T

    init_tables<<<4, 256>>>();
    cheaptrick_kernel<<<592, THREADS>>>(x, f0, sm, cp, out, n_rows);
}